// round 17
// baseline (speedup 1.0000x reference)
#include <cuda_runtime.h>
#include <cuda_fp16.h>
#include <math.h>

#define NN 100000
#define NE 3200000
#define DF 128
#define HID 16
#define NC 2
#define GEMM_BLKS 1563      // ceil(NN/64), 64 nodes per 256-thread block (4 lanes/node)
#define DEG_BLKS 205
#define FUSED_BLKS (GEMM_BLKS + DEG_BLKS)

// ---------------- scratch (no allocations allowed) ----------------
__device__ float    g_deg[NN];
__device__ float    g_dinv[NN];
__device__ float4   g_h1s[NN * 4];   // raw x@W1 (fp32)
__device__ uint4    g_h1h[NN * 2];   // scaled h1 as 16 halfs (2x uint4) per node
__device__ uint4    g_acc1h[NN * 2]; // layer-1 aggregate in fp16
__device__ unsigned g_h2h[NN];       // scaled h2 packed as half2
__device__ float2   g_acc2[NN];      // layer-2 aggregate, fp32

union HU { __half2 h; unsigned u; };

// ---------------- kernels ----------------

__global__ void k_init_deg() {
    int i = blockIdx.x * blockDim.x + threadIdx.x;
    if (i < NN) g_deg[i] = 1.0f;  // self-loop
}

// ---- FUSED: blocks [0,1563) = gemm1 (4 lanes/node, shfl x-broadcast);
//      blocks [1563,1768) = degree REDs.
// Lane (n,c): acc = 4 outputs [4c,4c+4); owns x chunk k=16k4+4c+j; other
// lanes' chunks arrive via shfl broadcast. W read: all lanes same k, c in
// 0..3 -> 4 distinct float4 addrs x 8-lane broadcast = conflict-free.
// regs ~46 (acc[4]+xv[8]) -> ~44 warps/SM; smem 8KB only.
__global__ void __launch_bounds__(256) k_fused(const float* __restrict__ x,
                                               const float* __restrict__ W1,
                                               const int* __restrict__ dst) {
    __shared__ __align__(16) float W1s[DF * HID];  // 8 KB
    int tid = threadIdx.x;

    if (blockIdx.x >= GEMM_BLKS) {
        int b = blockIdx.x - GEMM_BLKS;
        for (int e = b * 256 + tid; e < NE; e += DEG_BLKS * 256)
            atomicAdd(&g_deg[dst[e]], 1.0f);  // RED, no return
        return;
    }

    for (int i = tid; i < DF * HID; i += 256) W1s[i] = W1[i];
    __syncthreads();

    int lane = tid & 31;
    int c = lane & 3;
    int node = blockIdx.x * 64 + (tid >> 2);
    if (node >= NN) return;  // NN % 8 == 0: whole warp exits together

    const float4* xrow = (const float4*)(x + (size_t)node * DF);
    float4 xv[8];
#pragma unroll
    for (int k4 = 0; k4 < 8; k4++)
        xv[k4] = __ldg(&xrow[k4 * 4 + c]);   // interleaved: 8 lines/warp-LDG

    float a0 = 0.f, a1 = 0.f, a2 = 0.f, a3 = 0.f;
    const float* wb = &W1s[c * 4];           // + k*HID

#pragma unroll
    for (int k4 = 0; k4 < 8; k4++) {
#pragma unroll
        for (int cc = 0; cc < 4; cc++) {
            int srcl = (lane & ~3) | cc;
            float s0 = __shfl_sync(0xffffffffu, xv[k4].x, srcl);
            float s1 = __shfl_sync(0xffffffffu, xv[k4].y, srcl);
            float s2 = __shfl_sync(0xffffffffu, xv[k4].z, srcl);
            float s3 = __shfl_sync(0xffffffffu, xv[k4].w, srcl);
            int kb = k4 * 16 + cc * 4;       // k = kb + j
            float4 w0 = *(const float4*)&wb[(kb + 0) * HID];
            float4 w1 = *(const float4*)&wb[(kb + 1) * HID];
            float4 w2 = *(const float4*)&wb[(kb + 2) * HID];
            float4 w3 = *(const float4*)&wb[(kb + 3) * HID];
            a0 = fmaf(s0, w0.x, a0); a1 = fmaf(s0, w0.y, a1);
            a2 = fmaf(s0, w0.z, a2); a3 = fmaf(s0, w0.w, a3);
            a0 = fmaf(s1, w1.x, a0); a1 = fmaf(s1, w1.y, a1);
            a2 = fmaf(s1, w1.z, a2); a3 = fmaf(s1, w1.w, a3);
            a0 = fmaf(s2, w2.x, a0); a1 = fmaf(s2, w2.y, a1);
            a2 = fmaf(s2, w2.z, a2); a3 = fmaf(s2, w2.w, a3);
            a0 = fmaf(s3, w3.x, a0); a1 = fmaf(s3, w3.y, a1);
            a2 = fmaf(s3, w3.z, a2); a3 = fmaf(s3, w3.w, a3);
        }
    }

    float4 o; o.x = a0; o.y = a1; o.z = a2; o.w = a3;
    g_h1s[node * 4 + c] = o;   // raw; lanes -> consecutive float4s: coalesced
}

// dinv = rsqrt(deg); h1h = fp16-packed h1*dinv; acc1h init = same (self-loop).
__global__ void k_scale() {
    int i = blockIdx.x * blockDim.x + threadIdx.x;
    if (i >= NN) return;
    float di = rsqrtf(g_deg[i]);  // deg >= 1 always
    g_dinv[i] = di;
#pragma unroll
    for (int q = 0; q < 2; q++) {
        float4 a = g_h1s[i * 4 + q * 2 + 0];
        float4 b = g_h1s[i * 4 + q * 2 + 1];
        HU p0, p1, p2, p3;
        p0.h = __floats2half2_rn(a.x * di, a.y * di);
        p1.h = __floats2half2_rn(a.z * di, a.w * di);
        p2.h = __floats2half2_rn(b.x * di, b.y * di);
        p3.h = __floats2half2_rn(b.z * di, b.w * di);
        uint4 u = make_uint4(p0.u, p1.u, p2.u, p3.u);
        g_h1h[i * 2 + q] = u;
        g_acc1h[i * 2 + q] = u;   // self-loop init
    }
}

// ---- layer-1 scatter: 2 threads/edge; one uint4 gather + one v4.f16x2 RED ----
__global__ void k_scatter1(const int* __restrict__ src, const int* __restrict__ dst) {
    int t = blockIdx.x * blockDim.x + threadIdx.x;
    if (t >= NE * 2) return;
    int e = t >> 1;
    int c = t & 1;
    int s = src[e];
    int d = dst[e];
    uint4 u = g_h1h[s * 2 + c];
    uint4* p = &g_acc1h[d * 2 + c];
    asm volatile("red.global.add.noftz.v4.f16x2 [%0], {%1, %2, %3, %4};"
                 :: "l"(p), "r"(u.x), "r"(u.y), "r"(u.z), "r"(u.w)
                 : "memory");
}

// Per node: finish layer1 (scale + bias + relu), apply W2, pre-scale for layer2.
__global__ void k_finish1(const float* __restrict__ b1, const float* __restrict__ W2) {
    int i = blockIdx.x * blockDim.x + threadIdx.x;
    if (i >= NN) return;
    float di = g_dinv[i];
    float z0 = 0.0f, z1 = 0.0f;
#pragma unroll
    for (int q = 0; q < 2; q++) {
        uint4 u = g_acc1h[i * 2 + q];
        unsigned uu[4] = {u.x, u.y, u.z, u.w};
#pragma unroll
        for (int j = 0; j < 4; j++) {
            HU p; p.u = uu[j];
            float2 fv = __half22float2(p.h);
            int f = q * 8 + j * 2;
            float v0 = fmaxf(fmaf(di, fv.x, __ldg(&b1[f + 0])), 0.0f);
            float v1 = fmaxf(fmaf(di, fv.y, __ldg(&b1[f + 1])), 0.0f);
            z0 = fmaf(v0, __ldg(&W2[(f + 0) * NC + 0]), z0);
            z1 = fmaf(v0, __ldg(&W2[(f + 0) * NC + 1]), z1);
            z0 = fmaf(v1, __ldg(&W2[(f + 1) * NC + 0]), z0);
            z1 = fmaf(v1, __ldg(&W2[(f + 1) * NC + 1]), z1);
        }
    }
    float2 h;
    h.x = z0 * di;
    h.y = z1 * di;
    g_acc2[i] = h;                    // exact fp32 self-loop term
    HU p; p.h = __floats2half2_rn(h.x, h.y);
    g_h2h[i] = p.u;                   // fp16 scatter payload
}

// ---- layer-2 scatter: fp16 gather (4B), fp32 v2 RED (precision kept) ----
__global__ void k_scatter2(const int* __restrict__ src, const int* __restrict__ dst) {
    int e = blockIdx.x * blockDim.x + threadIdx.x;
    if (e >= NE) return;
    int s = src[e];
    int d = dst[e];
    HU p; p.u = g_h2h[s];
    float2 v = __half22float2(p.h);
    float2* q = &g_acc2[d];
    asm volatile("red.global.add.v2.f32 [%0], {%1, %2};"
                 :: "l"(q), "f"(v.x), "f"(v.y) : "memory");
}

// Finish layer 2 + log_softmax (2 classes).
__global__ void k_final(const float* __restrict__ b2, float* __restrict__ out) {
    int i = blockIdx.x * blockDim.x + threadIdx.x;
    if (i >= NN) return;
    float di = g_dinv[i];
    float2 a = g_acc2[i];
    float z0 = fmaf(di, a.x, __ldg(&b2[0]));
    float z1 = fmaf(di, a.y, __ldg(&b2[1]));
    float m = fmaxf(z0, z1);
    float lse = m + logf(expf(z0 - m) + expf(z1 - m));
    float2 o;
    o.x = z0 - lse;
    o.y = z1 - lse;
    ((float2*)out)[i] = o;
}

// ---------------- launch ----------------

extern "C" void kernel_launch(void* const* d_in, const int* in_sizes, int n_in,
                              void* d_out, int out_size) {
    const float* x = 0; const float* W1 = 0; const float* b1 = 0;
    const float* W2 = 0; const float* b2 = 0; const int* ei = 0;
    for (int i = 0; i < n_in; i++) {
        long long s = in_sizes[i];
        if (s == (long long)NN * DF)      x  = (const float*)d_in[i];
        else if (s == DF * HID)           W1 = (const float*)d_in[i];
        else if (s == HID)                b1 = (const float*)d_in[i];
        else if (s == HID * NC)           W2 = (const float*)d_in[i];
        else if (s == NC)                 b2 = (const float*)d_in[i];
        else if (s == 2LL * NE)           ei = (const int*)d_in[i];
    }
    const int* src = ei;        // row 0
    const int* dst = ei + NE;   // row 1

    const int T = 256;
    const int NBn = (NN + T - 1) / T;
    const int NBe = (NE + T - 1) / T;

    k_init_deg<<<NBn, T>>>();
    k_fused<<<FUSED_BLKS, 256>>>(x, W1, dst);   // gemm1 || degree REDs
    k_scale<<<NBn, T>>>();
    k_scatter1<<<(NE * 2 + T - 1) / T, T>>>(src, dst);
    k_finish1<<<NBn, T>>>(b1, W2);
    k_scatter2<<<NBe, T>>>(src, dst);
    k_final<<<NBn, T>>>(b2, (float*)d_out);
}